// round 10
// baseline (speedup 1.0000x reference)
#include <cuda_runtime.h>
#include <math.h>

#define NN 4
#define CC 26
#define NC 104
#define HH 512
#define WW 512
#define PH 171
#define PW 171
#define NY 169
#define NX 169
#define MTOT (NY*NX)
#define TS2 172         // gram smem tile row stride (float2 units)
#define SPLIT 8
#define RPP 22          // pooled-position rows per part (last part gets 15)
#define NBLK (NC*SPLIT)
#define GTHR 192        // gram block threads (3 position-groups x 2 product-halves)
#define PRB 2           // pool: output rows per block
#define RSTR 520        // pool: smem row stride (4 pad + 512 + 4)

typedef unsigned long long ull;

// scratch (static device arrays; no runtime allocation)
__device__ float g_pla[NC*PH*PW];      // pooled labels
__device__ float g_ppr[NC*PH*PW];      // pooled probs
__device__ float g_part[NBLK*192];     // per-block Gram partials (171 tri + 18 sums)
__device__ double g_rmi[NC];
__device__ int    g_cnt = 0;

// ---- f32x2 packed helpers (sm_103a FFMA2 via PTX) -------------------------
__device__ __forceinline__ ull pk2(float lo, float hi) {
    ull r; asm("mov.b64 %0,{%1,%2};" : "=l"(r) : "f"(lo), "f"(hi)); return r;
}
__device__ __forceinline__ void fma2(ull& acc, ull a, ull b) {
    asm("fma.rn.f32x2 %0,%1,%2,%0;" : "+l"(acc) : "l"(a), "l"(b));
}
__device__ __forceinline__ void add2(ull& acc, ull v) {
    asm("add.rn.f32x2 %0,%1,%0;" : "+l"(acc) : "l"(v));
}
__device__ __forceinline__ void upk2(ull v, float& lo, float& hi) {
    asm("mov.b64 {%0,%1},%2;" : "=f"(lo), "=f"(hi) : "l"(v));
}
__device__ __forceinline__ int tri_idx(int i, int j)  // i <= j, 18x18 upper tri
{
    return i*18 - (i*(i-1))/2 + (j - i);
}

// ---------------------------------------------------------------------------
// Kernel 1: mask + sigmoid + 3x3/stride3 max-pool, smem-staged (unchanged).
// ---------------------------------------------------------------------------
__global__ __launch_bounds__(256) void pool_kernel(const float* __restrict__ cls,
                                                   const float* __restrict__ tgt,
                                                   const float* __restrict__ valid)
{
    int nc  = blockIdx.y;
    int n   = nc / CC;
    int py0 = blockIdx.x * PRB;
    int t   = threadIdx.x;

    __shared__ float sT[6*RSTR];
    __shared__ float sX[6*RSTR];

    const float* cb = cls   + (size_t)nc * HH * WW;
    const float* tb = tgt   + (size_t)nc * HH * WW;
    const float* vb = valid + (size_t)n  * HH * WW;

    const float BIG = -3.0e38f;

    for (int q = t; q < 6*128; q += 256) {
        int i = q >> 7;
        int k = q & 127;
        int r = 3*py0 - 1 + i;
        float4 T4, X4;
        if ((unsigned)r < (unsigned)HH) {
            float4 c = ((const float4*)(cb + (size_t)r*WW))[k];
            float4 g = ((const float4*)(tb + (size_t)r*WW))[k];
            float4 v = ((const float4*)(vb + (size_t)r*WW))[k];
            T4.x = g.x*v.x; T4.y = g.y*v.y; T4.z = g.z*v.z; T4.w = g.w*v.w;
            X4.x = v.x > 0.0f ? c.x : BIG;
            X4.y = v.y > 0.0f ? c.y : BIG;
            X4.z = v.z > 0.0f ? c.z : BIG;
            X4.w = v.w > 0.0f ? c.w : BIG;
        } else {
            T4.x = T4.y = T4.z = T4.w = 0.0f;
            X4.x = X4.y = X4.z = X4.w = BIG;
        }
        *(float4*)&sT[i*RSTR + 4 + 4*k] = T4;
        *(float4*)&sX[i*RSTR + 4 + 4*k] = X4;
    }
    if (t < 6) { sT[t*RSTR + 3] = 0.0f; sX[t*RSTR + 3] = BIG; }
    __syncthreads();

    for (int o = t; o < PRB*PW; o += 256) {
        int pyl = o / PW, px = o - pyl*PW;
        int py  = py0 + pyl;
        if (py >= PH) continue;
        int base = pyl*3*RSTR + 3 + 3*px;
        float mla = 0.0f, mx = BIG;
        #pragma unroll
        for (int rr = 0; rr < 3; rr++) {
            int bb = base + rr*RSTR;
            #pragma unroll
            for (int cc = 0; cc < 3; cc++) {
                mla = fmaxf(mla, sT[bb + cc]);
                mx  = fmaxf(mx,  sX[bb + cc]);
            }
        }
        float pp = 1.0f/(1.0f + __expf(-mx)) + 1e-6f;
        size_t ob = (size_t)nc * (PH*PW) + (size_t)py*PW + px;
        g_pla[ob] = mla;
        g_ppr[ob] = pp;
    }
}

// ---------------------------------------------------------------------------
// Kernel 2 (v4): Gram pass on interleaved (la,pr) float2 tile.
// bc[i] = (la_i, pr_i) loaded via one LDS.64 — no packing.
//   Half A: fma2(acc, bc[i], bc[j]) -> (la_i la_j, pr_i pr_j): both symmetric
//           triangles (90 entries) in 45 FMA2s; add2 gives both view sums.
//   Half B: cross block la_i * pr_j: 5 packed la-row-pairs x 9 dup-pr -> 45 FMA2.
// 192 threads = 3 position-groups x 2 halves, occupancy 2.
// ---------------------------------------------------------------------------
__device__ __forceinline__ void load_bc(const ull* zp, int y, int x, ull bc[9])
{
    #pragma unroll
    for (int dy = 0; dy < 3; dy++) {
        int ro = (y + dy) * TS2 + x;
        bc[dy*3 + 0] = zp[ro + 0];
        bc[dy*3 + 1] = zp[ro + 1];
        bc[dy*3 + 2] = zp[ro + 2];
    }
}

__device__ __forceinline__ void gram_sym(const ull* zp, int pstart, int total,
                                         int lane, float* red)
{
    ull pacc[45], ssum2[9];
    #pragma unroll
    for (int k = 0; k < 45; k++) pacc[k] = 0ull;
    #pragma unroll
    for (int k = 0; k < 9; k++) ssum2[k] = 0ull;

    for (int p = pstart; p < total; p += 96) {
        int y = p / NX, x = p - y * NX;
        ull bc[9];
        load_bc(zp, y, x, bc);
        #pragma unroll
        for (int i = 0; i < 9; i++) add2(ssum2[i], bc[i]);
        int k = 0;
        #pragma unroll
        for (int i = 0; i < 9; i++)
            #pragma unroll
            for (int j = i; j < 9; j++) { fma2(pacc[k], bc[i], bc[j]); k++; }
    }

    #pragma unroll
    for (int k = 0; k < 45; k++) {
        ull v = pacc[k];
        #pragma unroll
        for (int o = 16; o; o >>= 1) { ull w = __shfl_xor_sync(0xffffffffu, v, o); add2(v, w); }
        pacc[k] = v;
    }
    #pragma unroll
    for (int k = 0; k < 9; k++) {
        ull v = ssum2[k];
        #pragma unroll
        for (int o = 16; o; o >>= 1) { ull w = __shfl_xor_sync(0xffffffffu, v, o); add2(v, w); }
        ssum2[k] = v;
    }

    if (lane == 0) {
        int k = 0;
        #pragma unroll
        for (int i = 0; i < 9; i++)
            #pragma unroll
            for (int j = i; j < 9; j++) {
                float ll, pp; upk2(pacc[k], ll, pp);
                atomicAdd(&red[tri_idx(i, j)],         ll);
                atomicAdd(&red[tri_idx(9 + i, 9 + j)], pp);
                k++;
            }
        #pragma unroll
        for (int i = 0; i < 9; i++) {
            float sl, sp; upk2(ssum2[i], sl, sp);
            atomicAdd(&red[171 + i], sl);
            atomicAdd(&red[180 + i], sp);
        }
    }
}

__device__ __forceinline__ void gram_cross(const ull* zp, int pstart, int total,
                                           int lane, float* red)
{
    ull cacc[45];
    #pragma unroll
    for (int k = 0; k < 45; k++) cacc[k] = 0ull;

    for (int p = pstart; p < total; p += 96) {
        int y = p / NX, x = p - y * NX;
        ull bc[9];
        load_bc(zp, y, x, bc);
        float la[9], pr[9];
        #pragma unroll
        for (int i = 0; i < 9; i++) upk2(bc[i], la[i], pr[i]);
        ull pj[9], Lp[5];
        #pragma unroll
        for (int j = 0; j < 9; j++) pj[j] = pk2(pr[j], pr[j]);
        #pragma unroll
        for (int r = 0; r < 4; r++) Lp[r] = pk2(la[2*r], la[2*r+1]);
        Lp[4] = pk2(la[8], 0.0f);
        #pragma unroll
        for (int r = 0; r < 5; r++)
            #pragma unroll
            for (int j = 0; j < 9; j++)
                fma2(cacc[r*9 + j], Lp[r], pj[j]);
    }

    #pragma unroll
    for (int k = 0; k < 45; k++) {
        ull v = cacc[k];
        #pragma unroll
        for (int o = 16; o; o >>= 1) { ull w = __shfl_xor_sync(0xffffffffu, v, o); add2(v, w); }
        cacc[k] = v;
    }

    if (lane == 0) {
        #pragma unroll
        for (int r = 0; r < 5; r++)
            #pragma unroll
            for (int j = 0; j < 9; j++) {
                float e0, e1; upk2(cacc[r*9 + j], e0, e1);
                atomicAdd(&red[tri_idx(2*r, 9 + j)], e0);
                if (r < 4) atomicAdd(&red[tri_idx(2*r + 1, 9 + j)], e1);
            }
    }
}

__global__ __launch_bounds__(GTHR, 2) void gram_kernel()
{
    int b    = blockIdx.x;
    int nc   = b >> 3;
    int part = b & 7;
    int y0   = part * RPP;
    int nyp  = min(RPP, NY - y0);
    int rows = nyp + 2;

    __shared__ float2 zp[(RPP+2)*TS2];   // 33 KB
    __shared__ float  red[192];

    const float* pla = g_pla + (size_t)nc * (PH*PW) + y0 * PW;
    const float* ppr = g_ppr + (size_t)nc * (PH*PW) + y0 * PW;
    for (int i = threadIdx.x; i < rows * PW; i += GTHR) {
        int rr = i / PW, cx = i - rr * PW;
        zp[rr*TS2 + cx] = make_float2(pla[i], ppr[i]);
    }
    if (threadIdx.x < 192) red[threadIdx.x] = 0.0f;
    __syncthreads();

    int warp  = threadIdx.x >> 5;
    int lane  = threadIdx.x & 31;
    int pairI = warp >> 1;          // 0..2
    int half  = warp & 1;
    int total = nyp * NX;
    int pstart = pairI * 32 + lane; // stride 96

    const ull* zpu = reinterpret_cast<const ull*>(zp);
    if (half == 0) gram_sym(zpu, pstart, total, lane, red);
    else           gram_cross(zpu, pstart, total, lane, red);

    __syncthreads();
    if (threadIdx.x < 189) g_part[(size_t)b * 192 + threadIdx.x] = red[threadIdx.x];
}

// ---------------------------------------------------------------------------
// Kernel 3: per-(n,c) 9x9 solve in fp64, block-parallel (192 threads).
// Last block (threadfence + counter) folds the final reduction. (unchanged)
// ---------------------------------------------------------------------------
__global__ __launch_bounds__(192) void solve_kernel(float* __restrict__ out)
{
    __shared__ float  red[192];
    __shared__ double A[81], La[81], W[81], Bm[81], sv[18];
    __shared__ double sm[128];
    __shared__ bool   isLast;

    int t = threadIdx.x, b = blockIdx.x;

    float a = 0.0f;
    if (t < 189) {
        #pragma unroll
        for (int p = 0; p < SPLIT; p++)
            a += g_part[(size_t)(b*SPLIT + p) * 192 + t];
    }
    red[t] = a;
    __syncthreads();
    if (t < 18) sv[t] = (double)red[171 + t];
    __syncthreads();

    const double invM = 1.0 / (double)MTOT;
    if (t < 81) {
        int d = t / 9, e = t % 9;
        int i, j;
        i = 9 + d; j = 9 + e; if (i > j) { int q = i; i = j; j = q; }
        A[t]  = (double)red[tri_idx(i, j)] - sv[9+d]*sv[9+e]*invM + (d == e ? 1e-3 : 0.0);
        i = d; j = e; if (i > j) { int q = i; i = j; j = q; }
        La[t] = (double)red[tri_idx(i, j)] - sv[d]*sv[e]*invM;
        W[t]  = (double)red[tri_idx(e, 9 + d)] - sv[e]*sv[9+d]*invM;
    }
    __syncthreads();

    if (t < 32) {
        #pragma unroll 1
        for (int j = 0; j < 9; j++) {
            if (t == 0) {
                double dd = A[j*9 + j];
                for (int k = 0; k < j; k++) dd -= A[j*9 + k]*A[j*9 + k];
                A[j*9 + j] = sqrt(fmax(dd, 1e-300));
            }
            __syncwarp();
            if (t > j && t < 9) {
                double v = A[t*9 + j];
                for (int k = 0; k < j; k++) v -= A[t*9 + k]*A[j*9 + k];
                A[t*9 + j] = v / A[j*9 + j];
            }
            __syncwarp();
        }
        #pragma unroll 1
        for (int f = 0; f < 9; f++) {
            if (t < 9) {
                double v = W[f*9 + t];
                for (int k = 0; k < f; k++) v -= A[f*9 + k]*W[k*9 + t];
                W[f*9 + t] = v / A[f*9 + f];
            }
            __syncwarp();
        }
    }
    __syncthreads();

    if (t < 81) {
        int d = t / 9, g = t % 9;
        double v = La[t];
        #pragma unroll
        for (int f = 0; f < 9; f++) v -= W[f*9 + d]*W[f*9 + g];
        Bm[t] = v + (d == g ? 1e-3 : 0.0);
    }
    __syncthreads();

    if (t < 32) {
        #pragma unroll 1
        for (int j = 0; j < 9; j++) {
            if (t == 0) {
                double dd = Bm[j*9 + j];
                for (int k = 0; k < j; k++) dd -= Bm[j*9 + k]*Bm[j*9 + k];
                Bm[j*9 + j] = sqrt(fmax(dd, 1e-300));
            }
            __syncwarp();
            if (t > j && t < 9) {
                double v = Bm[t*9 + j];
                for (int k = 0; k < j; k++) v -= Bm[t*9 + k]*Bm[j*9 + k];
                Bm[t*9 + j] = v / Bm[j*9 + j];
            }
            __syncwarp();
        }
        if (t == 0) {
            double r = 0.0;
            for (int j = 0; j < 9; j++) r += log(Bm[j*9 + j] + 1e-8);
            g_rmi[b] = r;   // == 0.5 * logdet
        }
    }
    __syncthreads();

    if (t == 0) {
        __threadfence();
        int old = atomicAdd(&g_cnt, 1);
        isLast = (old == NC - 1);
    }
    __syncthreads();
    if (isLast) {
        __threadfence();
        if (t < 128) sm[t] = (t < NC) ? g_rmi[t] : 0.0;
        __syncthreads();
        #pragma unroll
        for (int s = 64; s; s >>= 1) {
            if (t < s) sm[t] += sm[t + s];
            __syncthreads();
        }
        if (t == 0) {
            out[0] = (float)(sm[0] / 36.0);   // /4 (mean over n) /9 (HALF_D)
            g_cnt = 0;                        // reset for graph replay
        }
    }
}

// ---------------------------------------------------------------------------
extern "C" void kernel_launch(void* const* d_in, const int* in_sizes, int n_in,
                              void* d_out, int out_size)
{
    const float* cls   = (const float*)d_in[0];
    const float* tgt   = (const float*)d_in[1];
    const float* valid = (const float*)d_in[2];

    dim3 pg((PH + PRB - 1) / PRB, NC);
    pool_kernel<<<pg, 256>>>(cls, tgt, valid);
    gram_kernel<<<NBLK, GTHR>>>();
    solve_kernel<<<NC, 192>>>((float*)d_out);
}

// round 11
// speedup vs baseline: 1.0581x; 1.0581x over previous
#include <cuda_runtime.h>
#include <math.h>

#define NN 4
#define CC 26
#define NC 104
#define HH 512
#define WW 512
#define PH 171
#define PW 171
#define NY 169
#define NX 169
#define MTOT (NY*NX)
#define GSTR 176        // gram smem row stride (171 cols + 5 zero pad)
#define SPLIT 8
#define RPP 22          // pooled-position rows per part (last part gets 15)
#define NBLK (NC*SPLIT)
#define GTHR 192        // 6 warps = 2 position-groups x 3 triangle-thirds
#define PRB 2           // pool: output rows per block
#define RSTR 520        // pool: smem row stride (4 pad + 512 + 4)

// scratch (static device arrays; no runtime allocation)
__device__ float g_pla[NC*PH*PW];      // pooled labels
__device__ float g_ppr[NC*PH*PW];      // pooled probs
__device__ float g_part[NBLK*192];     // per-block Gram partials (171 tri + 18 sums)
__device__ double g_rmi[NC];
__device__ int    g_cnt = 0;

__device__ __forceinline__ int tri_idx(int i, int j)  // i <= j, 18x18 upper tri
{
    return i*18 - (i*(i-1))/2 + (j - i);
}

// ---------------------------------------------------------------------------
// Kernel 1: mask + sigmoid + 3x3/stride3 max-pool, smem-staged (unchanged).
// ---------------------------------------------------------------------------
__global__ __launch_bounds__(256) void pool_kernel(const float* __restrict__ cls,
                                                   const float* __restrict__ tgt,
                                                   const float* __restrict__ valid)
{
    int nc  = blockIdx.y;
    int n   = nc / CC;
    int py0 = blockIdx.x * PRB;
    int t   = threadIdx.x;

    __shared__ float sT[6*RSTR];
    __shared__ float sX[6*RSTR];

    const float* cb = cls   + (size_t)nc * HH * WW;
    const float* tb = tgt   + (size_t)nc * HH * WW;
    const float* vb = valid + (size_t)n  * HH * WW;

    const float BIG = -3.0e38f;

    for (int q = t; q < 6*128; q += 256) {
        int i = q >> 7;
        int k = q & 127;
        int r = 3*py0 - 1 + i;
        float4 T4, X4;
        if ((unsigned)r < (unsigned)HH) {
            float4 c = ((const float4*)(cb + (size_t)r*WW))[k];
            float4 g = ((const float4*)(tb + (size_t)r*WW))[k];
            float4 v = ((const float4*)(vb + (size_t)r*WW))[k];
            T4.x = g.x*v.x; T4.y = g.y*v.y; T4.z = g.z*v.z; T4.w = g.w*v.w;
            X4.x = v.x > 0.0f ? c.x : BIG;
            X4.y = v.y > 0.0f ? c.y : BIG;
            X4.z = v.z > 0.0f ? c.z : BIG;
            X4.w = v.w > 0.0f ? c.w : BIG;
        } else {
            T4.x = T4.y = T4.z = T4.w = 0.0f;
            X4.x = X4.y = X4.z = X4.w = BIG;
        }
        *(float4*)&sT[i*RSTR + 4 + 4*k] = T4;
        *(float4*)&sX[i*RSTR + 4 + 4*k] = X4;
    }
    if (t < 6) { sT[t*RSTR + 3] = 0.0f; sX[t*RSTR + 3] = BIG; }
    __syncthreads();

    for (int o = t; o < PRB*PW; o += 256) {
        int pyl = o / PW, px = o - pyl*PW;
        int py  = py0 + pyl;
        if (py >= PH) continue;
        int base = pyl*3*RSTR + 3 + 3*px;
        float mla = 0.0f, mx = BIG;
        #pragma unroll
        for (int rr = 0; rr < 3; rr++) {
            int bb = base + rr*RSTR;
            #pragma unroll
            for (int cc = 0; cc < 3; cc++) {
                mla = fmaxf(mla, sT[bb + cc]);
                mx  = fmaxf(mx,  sX[bb + cc]);
            }
        }
        float pp = 1.0f/(1.0f + __expf(-mx)) + 1e-6f;
        size_t ob = (size_t)nc * (PH*PW) + (size_t)py*PW + px;
        g_pla[ob] = mla;
        g_ppr[ob] = pp;
    }
}

// ---------------------------------------------------------------------------
// Kernel 2 (v5): direct Gram, scalar FFMA, 4-position runs, 3-way split.
// Each lane: run of 4 consecutive x positions in one row. 12 LDS.128 load
// all data for 4 z-windows. Warp third T accumulates tri entries
// [57T, 57T+57) + 6 view sums. 2 position-groups x 3 thirds per block.
// ---------------------------------------------------------------------------
template<int THIRD>
__device__ __forceinline__ void gram_third(const float* sLa, const float* sPr,
                                           int rstart, int nruns,
                                           int lane, float* red)
{
    const int KB = THIRD * 57;
    float acc[57], ssum[6];
    #pragma unroll
    for (int k = 0; k < 57; k++) acc[k] = 0.0f;
    #pragma unroll
    for (int k = 0; k < 6; k++) ssum[k] = 0.0f;

    for (int r = rstart; r < nruns; r += 64) {
        int row = r / 43;
        int cb  = (r - row*43) * 4;       // image x of first center

        float A[3][8], B[3][8];
        #pragma unroll
        for (int dy = 0; dy < 3; dy++) {
            const float* la = &sLa[(row + dy)*GSTR + cb];
            const float* pr = &sPr[(row + dy)*GSTR + cb];
            float4 l0 = *(const float4*)la;
            float4 l1 = *(const float4*)(la + 4);
            float4 p0 = *(const float4*)pr;
            float4 p1 = *(const float4*)(pr + 4);
            A[dy][0]=l0.x; A[dy][1]=l0.y; A[dy][2]=l0.z; A[dy][3]=l0.w;
            A[dy][4]=l1.x; A[dy][5]=l1.y; A[dy][6]=l1.z; A[dy][7]=l1.w;
            B[dy][0]=p0.x; B[dy][1]=p0.y; B[dy][2]=p0.z; B[dy][3]=p0.w;
            B[dy][4]=p1.x; B[dy][5]=p1.y; B[dy][6]=p1.z; B[dy][7]=p1.w;
        }

        #pragma unroll
        for (int p = 0; p < 4; p++) {
            if (cb + p < NX) {
                float z[18];
                #pragma unroll
                for (int dy = 0; dy < 3; dy++) {
                    z[dy*3 + 0]     = A[dy][p];
                    z[dy*3 + 1]     = A[dy][p+1];
                    z[dy*3 + 2]     = A[dy][p+2];
                    z[9 + dy*3 + 0] = B[dy][p];
                    z[9 + dy*3 + 1] = B[dy][p+1];
                    z[9 + dy*3 + 2] = B[dy][p+2];
                }
                int k = 0;
                #pragma unroll
                for (int i = 0; i < 18; i++)
                    #pragma unroll
                    for (int j = i; j < 18; j++) {
                        if (k >= KB && k < KB + 57) acc[k - KB] += z[i]*z[j];
                        k++;
                    }
                #pragma unroll
                for (int s = 0; s < 6; s++) ssum[s] += z[THIRD*6 + s];
            }
        }
    }

    // warp butterfly reduce
    #pragma unroll
    for (int k = 0; k < 57; k++) {
        float v = acc[k];
        #pragma unroll
        for (int o = 16; o; o >>= 1) v += __shfl_xor_sync(0xffffffffu, v, o);
        acc[k] = v;
    }
    #pragma unroll
    for (int k = 0; k < 6; k++) {
        float v = ssum[k];
        #pragma unroll
        for (int o = 16; o; o >>= 1) v += __shfl_xor_sync(0xffffffffu, v, o);
        ssum[k] = v;
    }

    if (lane == 0) {
        #pragma unroll
        for (int q = 0; q < 57; q++) atomicAdd(&red[KB + q], acc[q]);
        #pragma unroll
        for (int s = 0; s < 6; s++)  atomicAdd(&red[171 + THIRD*6 + s], ssum[s]);
    }
}

__global__ __launch_bounds__(GTHR, 2) void gram_kernel()
{
    int b    = blockIdx.x;
    int nc   = b >> 3;
    int part = b & 7;
    int y0   = part * RPP;
    int nyp  = min(RPP, NY - y0);
    int rows = nyp + 2;

    __shared__ float sLa[(RPP+2)*GSTR];
    __shared__ float sPr[(RPP+2)*GSTR];
    __shared__ float red[192];

    const float* pla = g_pla + (size_t)nc * (PH*PW) + y0 * PW;
    const float* ppr = g_ppr + (size_t)nc * (PH*PW) + y0 * PW;
    for (int i = threadIdx.x; i < rows * GSTR; i += GTHR) {
        int rr = i / GSTR, cx = i - rr * GSTR;
        float lv = 0.0f, pv = 0.0f;
        if (cx < PW) {
            lv = pla[(size_t)rr*PW + cx];
            pv = ppr[(size_t)rr*PW + cx];
        }
        sLa[i] = lv; sPr[i] = pv;
    }
    if (threadIdx.x < 192) red[threadIdx.x] = 0.0f;
    __syncthreads();

    int warp  = threadIdx.x >> 5;
    int lane  = threadIdx.x & 31;
    int third = warp % 3;
    int group = warp / 3;            // 0 or 1
    int nruns = nyp * 43;
    int rstart = group * 32 + lane;  // stride 64

    if      (third == 0) gram_third<0>(sLa, sPr, rstart, nruns, lane, red);
    else if (third == 1) gram_third<1>(sLa, sPr, rstart, nruns, lane, red);
    else                 gram_third<2>(sLa, sPr, rstart, nruns, lane, red);

    __syncthreads();
    if (threadIdx.x < 189) g_part[(size_t)b * 192 + threadIdx.x] = red[threadIdx.x];
}

// ---------------------------------------------------------------------------
// Kernel 3: per-(n,c) 9x9 solve in fp64, block-parallel (192 threads).
// Last block (threadfence + counter) folds the final reduction. (unchanged)
// ---------------------------------------------------------------------------
__global__ __launch_bounds__(192) void solve_kernel(float* __restrict__ out)
{
    __shared__ float  red[192];
    __shared__ double A[81], La[81], W[81], Bm[81], sv[18];
    __shared__ double sm[128];
    __shared__ bool   isLast;

    int t = threadIdx.x, b = blockIdx.x;

    float a = 0.0f;
    if (t < 189) {
        #pragma unroll
        for (int p = 0; p < SPLIT; p++)
            a += g_part[(size_t)(b*SPLIT + p) * 192 + t];
    }
    red[t] = a;
    __syncthreads();
    if (t < 18) sv[t] = (double)red[171 + t];
    __syncthreads();

    const double invM = 1.0 / (double)MTOT;
    if (t < 81) {
        int d = t / 9, e = t % 9;
        int i, j;
        i = 9 + d; j = 9 + e; if (i > j) { int q = i; i = j; j = q; }
        A[t]  = (double)red[tri_idx(i, j)] - sv[9+d]*sv[9+e]*invM + (d == e ? 1e-3 : 0.0);
        i = d; j = e; if (i > j) { int q = i; i = j; j = q; }
        La[t] = (double)red[tri_idx(i, j)] - sv[d]*sv[e]*invM;
        W[t]  = (double)red[tri_idx(e, 9 + d)] - sv[e]*sv[9+d]*invM;
    }
    __syncthreads();

    if (t < 32) {
        #pragma unroll 1
        for (int j = 0; j < 9; j++) {
            if (t == 0) {
                double dd = A[j*9 + j];
                for (int k = 0; k < j; k++) dd -= A[j*9 + k]*A[j*9 + k];
                A[j*9 + j] = sqrt(fmax(dd, 1e-300));
            }
            __syncwarp();
            if (t > j && t < 9) {
                double v = A[t*9 + j];
                for (int k = 0; k < j; k++) v -= A[t*9 + k]*A[j*9 + k];
                A[t*9 + j] = v / A[j*9 + j];
            }
            __syncwarp();
        }
        #pragma unroll 1
        for (int f = 0; f < 9; f++) {
            if (t < 9) {
                double v = W[f*9 + t];
                for (int k = 0; k < f; k++) v -= A[f*9 + k]*W[k*9 + t];
                W[f*9 + t] = v / A[f*9 + f];
            }
            __syncwarp();
        }
    }
    __syncthreads();

    if (t < 81) {
        int d = t / 9, g = t % 9;
        double v = La[t];
        #pragma unroll
        for (int f = 0; f < 9; f++) v -= W[f*9 + d]*W[f*9 + g];
        Bm[t] = v + (d == g ? 1e-3 : 0.0);
    }
    __syncthreads();

    if (t < 32) {
        #pragma unroll 1
        for (int j = 0; j < 9; j++) {
            if (t == 0) {
                double dd = Bm[j*9 + j];
                for (int k = 0; k < j; k++) dd -= Bm[j*9 + k]*Bm[j*9 + k];
                Bm[j*9 + j] = sqrt(fmax(dd, 1e-300));
            }
            __syncwarp();
            if (t > j && t < 9) {
                double v = Bm[t*9 + j];
                for (int k = 0; k < j; k++) v -= Bm[t*9 + k]*Bm[j*9 + k];
                Bm[t*9 + j] = v / Bm[j*9 + j];
            }
            __syncwarp();
        }
        if (t == 0) {
            double r = 0.0;
            for (int j = 0; j < 9; j++) r += log(Bm[j*9 + j] + 1e-8);
            g_rmi[b] = r;   // == 0.5 * logdet
        }
    }
    __syncthreads();

    if (t == 0) {
        __threadfence();
        int old = atomicAdd(&g_cnt, 1);
        isLast = (old == NC - 1);
    }
    __syncthreads();
    if (isLast) {
        __threadfence();
        if (t < 128) sm[t] = (t < NC) ? g_rmi[t] : 0.0;
        __syncthreads();
        #pragma unroll
        for (int s = 64; s; s >>= 1) {
            if (t < s) sm[t] += sm[t + s];
            __syncthreads();
        }
        if (t == 0) {
            out[0] = (float)(sm[0] / 36.0);   // /4 (mean over n) /9 (HALF_D)
            g_cnt = 0;                        // reset for graph replay
        }
    }
}

// ---------------------------------------------------------------------------
extern "C" void kernel_launch(void* const* d_in, const int* in_sizes, int n_in,
                              void* d_out, int out_size)
{
    const float* cls   = (const float*)d_in[0];
    const float* tgt   = (const float*)d_in[1];
    const float* valid = (const float*)d_in[2];

    dim3 pg((PH + PRB - 1) / PRB, NC);
    pool_kernel<<<pg, 256>>>(cls, tgt, valid);
    gram_kernel<<<NBLK, GTHR>>>();
    solve_kernel<<<NC, 192>>>((float*)d_out);
}